// round 8
// baseline (speedup 1.0000x reference)
#include <cuda_runtime.h>

typedef unsigned long long ull;

#define NSAMP 4096
#define DIM   256
#define NCLS  6

#define BM 128
#define BN 128
#define BK 16

// ---------------- device scratch (no allocations allowed) ----------------
__device__ float  g_ss[NSAMP];           // ||source_i||^2
__device__ float  g_tt[NSAMP];           // ||target_j||^2
__device__ float  g_colsum[DIM];         // column sums of concat(S,T)
__device__ double g_sqsum;               // sum of all squared norms
__device__ float  g_neg_inv_bw16;        // -1/(bandwidth*16)
__device__ ull    g_min_row[NSAMP];      // per source row: packed (d2,target idx)
__device__ ull    g_min_col[NSAMP];      // per target col: packed (d2,source idx)
__device__ double g_ksum[3];             // SS, TT, ST kernel sums
__device__ double g_clf_sum;
__device__ double g_dis_sum;
__device__ int    g_label64;

// ---------------- init ----------------
__global__ void init_kernel() {
    int i = blockIdx.x * blockDim.x + threadIdx.x;
    if (i < NSAMP) { g_min_row[i] = ~0ull; g_min_col[i] = ~0ull; }
    if (i < DIM)   g_colsum[i] = 0.f;
    if (i < 3)     g_ksum[i] = 0.0;
    if (i == 0)    { g_sqsum = 0.0; g_clf_sum = 0.0; g_dis_sum = 0.0; }
}

// Detect whether labels are serialized as int64 (odd 32-bit words all zero)
// or int32. Safe: we only scan the first 4096 words, valid in both cases.
__global__ void detect_labels(const int* __restrict__ w) {
    __shared__ int any;
    if (threadIdx.x == 0) any = 0;
    __syncthreads();
    for (int i = 1 + 2 * threadIdx.x; i < NSAMP; i += 2 * blockDim.x)
        if (w[i] != 0) any = 1;
    __syncthreads();
    if (threadIdx.x == 0) g_label64 = (any == 0) ? 1 : 0;
}

// ---------------- row norms + total squared sum ----------------
__global__ void row_norms(const float* __restrict__ S, const float* __restrict__ T) {
    int r = blockIdx.x;            // 0..8191
    const float* X = (r < NSAMP) ? (S + (size_t)r * DIM)
                                 : (T + (size_t)(r - NSAMP) * DIM);
    float v = X[threadIdx.x];
    float sq = v * v;
    for (int o = 16; o; o >>= 1) sq += __shfl_down_sync(0xffffffffu, sq, o);
    __shared__ float ws[8];
    if ((threadIdx.x & 31) == 0) ws[threadIdx.x >> 5] = sq;
    __syncthreads();
    if (threadIdx.x == 0) {
        float tot = 0.f;
        #pragma unroll
        for (int k = 0; k < 8; k++) tot += ws[k];
        if (r < NSAMP) g_ss[r] = tot; else g_tt[r - NSAMP] = tot;
        atomicAdd(&g_sqsum, (double)tot);
    }
}

// ---------------- column sums of concat(S,T) ----------------
__global__ void col_sums(const float* __restrict__ S, const float* __restrict__ T) {
    int c  = threadIdx.x;          // 0..255
    int r0 = blockIdx.x * 128;     // 64 blocks * 128 rows = 8192
    float acc = 0.f;
    for (int r = r0; r < r0 + 128; r++) {
        const float* X = (r < NSAMP) ? (S + (size_t)r * DIM)
                                     : (T + (size_t)(r - NSAMP) * DIM);
        acc += X[c];
    }
    atomicAdd(&g_colsum[c], acc);
}

// ---------------- bandwidth: sum(l2) = 2n*sum(sq) - 2*||colsum||^2 ----------------
__global__ void bandwidth_kernel() {
    float cs = g_colsum[threadIdx.x];
    double p = (double)cs * (double)cs;
    for (int o = 16; o; o >>= 1) p += __shfl_down_sync(0xffffffffu, p, o);
    __shared__ double ws[8];
    if ((threadIdx.x & 31) == 0) ws[threadIdx.x >> 5] = p;
    __syncthreads();
    if (threadIdx.x == 0) {
        double ssv = 0.0;
        #pragma unroll
        for (int k = 0; k < 8; k++) ssv += ws[k];
        double n = 2.0 * NSAMP;
        double sumL2 = 2.0 * n * g_sqsum - 2.0 * ssv;
        double b = sumL2 / (n * n - n) / 4.0;   // / KERNEL_MUL^(KERNEL_NUM//2)
        g_neg_inv_bw16 = (float)(-1.0 / (b * 16.0));
    }
}

// ---------------- cross entropy ----------------
__global__ void clf_kernel(const float* __restrict__ sclf, const int* __restrict__ lw) {
    int i = blockIdx.x * blockDim.x + threadIdx.x;
    float loss = 0.f;
    if (i < NSAMP) {
        const float* x = sclf + i * NCLS;
        float m = x[0];
        #pragma unroll
        for (int c = 1; c < NCLS; c++) m = fmaxf(m, x[c]);
        float se = 0.f;
        #pragma unroll
        for (int c = 0; c < NCLS; c++) se += __expf(x[c] - m);
        float lse = m + __logf(se);
        int lab = g_label64 ? lw[2 * i] : lw[i];
        loss = lse - x[lab];
    }
    for (int o = 16; o; o >>= 1) loss += __shfl_down_sync(0xffffffffu, loss, o);
    if ((threadIdx.x & 31) == 0) atomicAdd(&g_clf_sum, (double)loss);
}

// ---------------- fused pairwise-distance GEMM + MMD kernel sum + argmin ----------------
// MODE 0: S x S (symmetric, upper triangle, weight 2 off-diag)
// MODE 1: T x T (same)
// MODE 2: S x T (full; also tracks row/col argmin of clamped d2)
template <int MODE>
__global__ __launch_bounds__(256, 2)
void pair_kernel(const float* __restrict__ A, const float* __restrict__ B) {
    int bi = blockIdx.y, bj = blockIdx.x;
    if (MODE != 2 && bi > bj) return;

    __shared__ __align__(16) float As[BK][BM];
    __shared__ __align__(16) float Bs[BK][BN];

    int tid = threadIdx.x;
    int tx = tid & 15, ty = tid >> 4;
    int rowA0 = bi * BM, rowB0 = bj * BN;

    int lr = tid >> 2;           // 0..63
    int lc = (tid & 3) << 2;     // 0,4,8,12

    const float* pA = A + (size_t)(rowA0 + lr) * DIM + lc;
    const float* pB = B + (size_t)(rowB0 + lr) * DIM + lc;

    float acc[8][8];
    #pragma unroll
    for (int i = 0; i < 8; i++)
        #pragma unroll
        for (int j = 0; j < 8; j++) acc[i][j] = 0.f;

    // prefetch first k-tile into registers
    float4 a0 = *(const float4*)(pA);
    float4 a1 = *(const float4*)(pA + 64 * DIM);
    float4 b0 = *(const float4*)(pB);
    float4 b1 = *(const float4*)(pB + 64 * DIM);

    for (int k0 = 0; k0 < DIM; k0 += BK) {
        // stage current tile into smem (transposed: As[k][m])
        As[lc + 0][lr]      = a0.x; As[lc + 1][lr]      = a0.y;
        As[lc + 2][lr]      = a0.z; As[lc + 3][lr]      = a0.w;
        As[lc + 0][lr + 64] = a1.x; As[lc + 1][lr + 64] = a1.y;
        As[lc + 2][lr + 64] = a1.z; As[lc + 3][lr + 64] = a1.w;
        Bs[lc + 0][lr]      = b0.x; Bs[lc + 1][lr]      = b0.y;
        Bs[lc + 2][lr]      = b0.z; Bs[lc + 3][lr]      = b0.w;
        Bs[lc + 0][lr + 64] = b1.x; Bs[lc + 1][lr + 64] = b1.y;
        Bs[lc + 2][lr + 64] = b1.z; Bs[lc + 3][lr + 64] = b1.w;
        __syncthreads();

        // prefetch next tile while computing
        if (k0 + BK < DIM) {
            a0 = *(const float4*)(pA + k0 + BK);
            a1 = *(const float4*)(pA + 64 * DIM + k0 + BK);
            b0 = *(const float4*)(pB + k0 + BK);
            b1 = *(const float4*)(pB + 64 * DIM + k0 + BK);
        }

        #pragma unroll
        for (int k = 0; k < BK; ++k) {
            float4 x0 = *(const float4*)&As[k][ty * 8];
            float4 x1 = *(const float4*)&As[k][ty * 8 + 4];
            float4 y0 = *(const float4*)&Bs[k][tx * 8];
            float4 y1 = *(const float4*)&Bs[k][tx * 8 + 4];
            float ra[8] = {x0.x, x0.y, x0.z, x0.w, x1.x, x1.y, x1.z, x1.w};
            float rb[8] = {y0.x, y0.y, y0.z, y0.w, y1.x, y1.y, y1.z, y1.w};
            #pragma unroll
            for (int i = 0; i < 8; i++)
                #pragma unroll
                for (int j = 0; j < 8; j++)
                    acc[i][j] = fmaf(ra[i], rb[j], acc[i][j]);
        }
        __syncthreads();
    }

    // ---- epilogue ----
    const float* nA = (MODE == 1) ? g_tt : g_ss;
    const float* nB = (MODE == 0) ? g_ss : g_tt;
    float nib = g_neg_inv_bw16;
    float na[8], nb[8];
    #pragma unroll
    for (int i = 0; i < 8; i++) na[i] = nA[rowA0 + ty * 8 + i];
    #pragma unroll
    for (int j = 0; j < 8; j++) nb[j] = nB[rowB0 + tx * 8 + j];

    float part = 0.f;

    if (MODE == 2) {
        __shared__ ull sRow[BM];
        __shared__ ull sCol[BN];
        for (int t = tid; t < BM; t += 256) sRow[t] = ~0ull;
        for (int t = tid; t < BN; t += 256) sCol[t] = ~0ull;
        __syncthreads();

        ull colbest[8];
        #pragma unroll
        for (int j = 0; j < 8; j++) colbest[j] = ~0ull;

        #pragma unroll
        for (int i = 0; i < 8; i++) {
            ull rowbest = ~0ull;
            unsigned gi = (unsigned)(rowA0 + ty * 8 + i);
            #pragma unroll
            for (int j = 0; j < 8; j++) {
                float d2 = na[i] + nb[j] - 2.f * acc[i][j];
                float e  = __expf(d2 * nib);
                float e2 = e * e, e4 = e2 * e2, e8 = e4 * e4, e16 = e8 * e8;
                part += e + e2 + e4 + e8 + e16;

                float d2c = fmaxf(d2, 0.f);
                unsigned fb = __float_as_uint(d2c);
                ull kr = ((ull)fb << 32) | (unsigned)(rowB0 + tx * 8 + j);
                if (kr < rowbest) rowbest = kr;
                ull kc = ((ull)fb << 32) | gi;
                if (kc < colbest[j]) colbest[j] = kc;
            }
            atomicMin(&sRow[ty * 8 + i], rowbest);
        }
        #pragma unroll
        for (int j = 0; j < 8; j++) atomicMin(&sCol[tx * 8 + j], colbest[j]);
        __syncthreads();
        if (tid < BM)      atomicMin(&g_min_row[rowA0 + tid], sRow[tid]);
        else               atomicMin(&g_min_col[rowB0 + tid - BM], sCol[tid - BM]);
    } else {
        #pragma unroll
        for (int i = 0; i < 8; i++)
            #pragma unroll
            for (int j = 0; j < 8; j++) {
                float d2 = na[i] + nb[j] - 2.f * acc[i][j];
                float e  = __expf(d2 * nib);
                float e2 = e * e, e4 = e2 * e2, e8 = e4 * e4, e16 = e8 * e8;
                part += e + e2 + e4 + e8 + e16;
            }
        if (bi != bj) part *= 2.f;   // account for the mirrored tile
    }

    for (int o = 16; o; o >>= 1) part += __shfl_down_sync(0xffffffffu, part, o);
    if ((tid & 31) == 0) atomicAdd(&g_ksum[MODE], (double)part);
}

// ---------------- distillation losses ----------------
__device__ __forceinline__ float distill_row(const float* te, const float* st) {
    float mt = te[0], ms = st[0];
    #pragma unroll
    for (int c = 1; c < NCLS; c++) { mt = fmaxf(mt, te[c]); ms = fmaxf(ms, st[c]); }
    float set = 0.f, ses = 0.f;
    #pragma unroll
    for (int c = 0; c < NCLS; c++) { set += __expf(te[c] - mt); ses += __expf(st[c] - ms); }
    float lses = ms + __logf(ses);
    float inv = 1.f / set;
    float acc = 0.f;
    #pragma unroll
    for (int c = 0; c < NCLS; c++)
        acc += __expf(te[c] - mt) * inv * (lses - st[c]);
    return acc;
}

__global__ void dis_kernel(const float* __restrict__ sclf, const float* __restrict__ tclf) {
    int i = blockIdx.x * blockDim.x + threadIdx.x;
    float loss = 0.f;
    if (i < NSAMP) {
        int mi  = (int)(g_min_row[i] & 0xffffffffull);  // nearest target of source i
        int mti = (int)(g_min_col[i] & 0xffffffffull);  // nearest source of target i
        loss = distill_row(sclf + i * NCLS, tclf + mi * NCLS)
             + distill_row(sclf + mti * NCLS, tclf + i * NCLS);
    }
    for (int o = 16; o; o >>= 1) loss += __shfl_down_sync(0xffffffffu, loss, o);
    if ((threadIdx.x & 31) == 0) atomicAdd(&g_dis_sum, (double)loss);
}

__global__ void finalize_kernel(float* __restrict__ out) {
    out[0] = (float)(g_clf_sum / (double)NSAMP);
    out[1] = (float)(g_dis_sum / (double)NSAMP);
    out[2] = (float)((g_ksum[0] + g_ksum[1] - 2.0 * g_ksum[2]) /
                     ((double)NSAMP * (double)NSAMP));
}

// ---------------- launch ----------------
extern "C" void kernel_launch(void* const* d_in, const int* in_sizes, int n_in,
                              void* d_out, int out_size) {
    const float* S    = (const float*)d_in[0];
    const float* T    = (const float*)d_in[1];
    const float* sclf = (const float*)d_in[2];
    const float* tclf = (const float*)d_in[3];
    const int*   lab  = (const int*)d_in[4];
    float* out = (float*)d_out;

    init_kernel<<<16, 256>>>();
    detect_labels<<<1, 256>>>(lab);
    row_norms<<<2 * NSAMP, 256>>>(S, T);
    col_sums<<<64, 256>>>(S, T);
    bandwidth_kernel<<<1, 256>>>();
    clf_kernel<<<16, 256>>>(sclf, lab);

    dim3 grid(NSAMP / BN, NSAMP / BM);
    pair_kernel<0><<<grid, 256>>>(S, S);
    pair_kernel<1><<<grid, 256>>>(T, T);
    pair_kernel<2><<<grid, 256>>>(S, T);

    dis_kernel<<<16, 256>>>(sclf, tclf);
    finalize_kernel<<<1, 1>>>(out);
}

// round 10
// speedup vs baseline: 2.5640x; 2.5640x over previous
#include <cuda_runtime.h>
#include <cuda_bf16.h>

typedef unsigned long long ull;
typedef unsigned int u32;

#define NSAMP 4096
#define DIM   256
#define NCLS  6
#define TDIM  128
#define KC    64
#define NCH   (DIM / KC)            // 4
#define OPB   (TDIM * KC * 2)       // 16384 bytes per operand tile
#define STAGEB (4 * OPB)            // 65536 per stage (Ah,Al,Bh,Bl)
#define SMEM_DYN (2 * STAGEB + 1024)

// ---------------- device scratch ----------------
__device__ __align__(1024) __nv_bfloat16 g_Sh[NSAMP * DIM];
__device__ __align__(1024) __nv_bfloat16 g_Sl[NSAMP * DIM];
__device__ __align__(1024) __nv_bfloat16 g_Th[NSAMP * DIM];
__device__ __align__(1024) __nv_bfloat16 g_Tl[NSAMP * DIM];
__device__ float  g_ss[NSAMP];
__device__ float  g_tt[NSAMP];
__device__ float  g_colsum[DIM];
__device__ double g_sqsum;
__device__ float  g_neg_inv_bw16;
__device__ ull    g_min_row[NSAMP];
__device__ ull    g_min_col[NSAMP];
__device__ double g_ksum[3];
__device__ double g_clf_sum;
__device__ double g_dis_sum;
__device__ int    g_label64;

// ---------------- PTX helpers (all baseline, no 'a'-gated features) ----------------
__device__ __forceinline__ u32 smem_u32(const void* p) {
    u32 a;
    asm("{ .reg .u64 t; cvta.to.shared.u64 t, %1; cvt.u32.u64 %0, t; }" : "=r"(a) : "l"(p));
    return a;
}

__device__ __forceinline__ void cp16(u32 dst, const void* src) {
    asm volatile("cp.async.cg.shared.global [%0], [%1], 16;" :: "r"(dst), "l"(src));
}
#define CP_COMMIT() asm volatile("cp.async.commit_group;")
#define CP_WAIT(n)  asm volatile("cp.async.wait_group %0;" :: "n"(n))

__device__ __forceinline__ void ldsm4(u32* r, u32 addr) {
    asm volatile("ldmatrix.sync.aligned.m8n8.x4.shared.b16 {%0,%1,%2,%3}, [%4];"
        : "=r"(r[0]), "=r"(r[1]), "=r"(r[2]), "=r"(r[3]) : "r"(addr));
}

__device__ __forceinline__ void hmma(float* d, const u32* a, const u32* b) {
    asm volatile(
        "mma.sync.aligned.m16n8k16.row.col.f32.bf16.bf16.f32 "
        "{%0,%1,%2,%3}, {%4,%5,%6,%7}, {%8,%9}, {%0,%1,%2,%3};"
        : "+f"(d[0]), "+f"(d[1]), "+f"(d[2]), "+f"(d[3])
        : "r"(a[0]), "r"(a[1]), "r"(a[2]), "r"(a[3]), "r"(b[0]), "r"(b[1]));
}

// 128B-row XOR swizzle: bits[6:4] ^= bits[9:7]  (row & 7)
__device__ __forceinline__ u32 swz(u32 row, u32 colbytes) {
    u32 off = row * 128u + colbytes;
    return off ^ ((off >> 3) & 0x70u);
}

// ---------------- small kernels ----------------
__global__ void init_kernel() {
    int i = blockIdx.x * blockDim.x + threadIdx.x;
    if (i < NSAMP) { g_min_row[i] = ~0ull; g_min_col[i] = ~0ull; }
    if (i < DIM)   g_colsum[i] = 0.f;
    if (i < 3)     g_ksum[i] = 0.0;
    if (i == 0)    { g_sqsum = 0.0; g_clf_sum = 0.0; g_dis_sum = 0.0; }
}

__global__ void detect_labels(const int* __restrict__ w) {
    __shared__ int any;
    if (threadIdx.x == 0) any = 0;
    __syncthreads();
    for (int i = 1 + 2 * threadIdx.x; i < NSAMP; i += 2 * blockDim.x)
        if (w[i] != 0) any = 1;
    __syncthreads();
    if (threadIdx.x == 0) g_label64 = (any == 0) ? 1 : 0;
}

// fused: bf16 hi/lo split + row norms + column sums + total squared sum
__global__ void preprocess(const float* __restrict__ S, const float* __restrict__ T) {
    __shared__ float tile[32][DIM + 1];
    int r0 = blockIdx.x * 32;
    bool isS = (r0 < NSAMP);
    int rloc = isS ? r0 : (r0 - NSAMP);
    const float* X = isS ? (S + (size_t)r0 * DIM) : (T + (size_t)rloc * DIM);
    __nv_bfloat16* H = isS ? (g_Sh + (size_t)r0 * DIM) : (g_Th + (size_t)rloc * DIM);
    __nv_bfloat16* L = isS ? (g_Sl + (size_t)r0 * DIM) : (g_Tl + (size_t)rloc * DIM);

    int tid = threadIdx.x;
    for (int i = tid; i < 32 * DIM; i += 256) {
        float v = X[i];
        tile[i >> 8][i & 255] = v;
        __nv_bfloat16 h = __float2bfloat16(v);
        H[i] = h;
        L[i] = __float2bfloat16(v - __bfloat162float(h));
    }
    __syncthreads();

    int wid = tid >> 5, lane = tid & 31;
    float dsum = 0.f;
    #pragma unroll
    for (int q = 0; q < 4; q++) {
        int rr = wid * 4 + q;
        float s = 0.f;
        for (int c = lane; c < DIM; c += 32) { float v = tile[rr][c]; s += v * v; }
        for (int o = 16; o; o >>= 1) s += __shfl_down_sync(0xffffffffu, s, o);
        if (lane == 0) {
            if (isS) g_ss[r0 + rr] = s; else g_tt[rloc + rr] = s;
            dsum += s;
        }
    }
    if (lane == 0) atomicAdd(&g_sqsum, (double)dsum);

    float cs = 0.f;
    #pragma unroll
    for (int rr = 0; rr < 32; rr++) cs += tile[rr][tid];
    atomicAdd(&g_colsum[tid], cs);
}

__global__ void bandwidth_kernel() {
    float cs = g_colsum[threadIdx.x];
    double p = (double)cs * (double)cs;
    for (int o = 16; o; o >>= 1) p += __shfl_down_sync(0xffffffffu, p, o);
    __shared__ double ws[8];
    if ((threadIdx.x & 31) == 0) ws[threadIdx.x >> 5] = p;
    __syncthreads();
    if (threadIdx.x == 0) {
        double ssv = 0.0;
        #pragma unroll
        for (int k = 0; k < 8; k++) ssv += ws[k];
        double n = 2.0 * NSAMP;
        double sumL2 = 2.0 * n * g_sqsum - 2.0 * ssv;
        double b = sumL2 / (n * n - n) / 4.0;
        g_neg_inv_bw16 = (float)(-1.0 / (b * 16.0));
    }
}

__global__ void clf_kernel(const float* __restrict__ sclf, const int* __restrict__ lw) {
    int i = blockIdx.x * blockDim.x + threadIdx.x;
    float loss = 0.f;
    if (i < NSAMP) {
        const float* x = sclf + i * NCLS;
        float m = x[0];
        #pragma unroll
        for (int c = 1; c < NCLS; c++) m = fmaxf(m, x[c]);
        float se = 0.f;
        #pragma unroll
        for (int c = 0; c < NCLS; c++) se += __expf(x[c] - m);
        float lse = m + __logf(se);
        int lab = g_label64 ? lw[2 * i] : lw[i];
        loss = lse - x[lab];
    }
    for (int o = 16; o; o >>= 1) loss += __shfl_down_sync(0xffffffffu, loss, o);
    if ((threadIdx.x & 31) == 0) atomicAdd(&g_clf_sum, (double)loss);
}

// ---------------- mma.sync pair kernel ----------------
// MODE 0: SxS (triangular, x2 off-diag)  MODE 1: TxT  MODE 2: SxT (+argmin)
template <int MODE>
__global__ __launch_bounds__(256, 1) void pair_mma() {
    int bi = blockIdx.y, bj = blockIdx.x;
    if (MODE != 2 && bi > bj) return;

    extern __shared__ char dynraw[];
    __shared__ float naS[TDIM], nbS[TDIM];
    __shared__ ull   sRow[TDIM], sCol[TDIM];

    int tid = threadIdx.x, wid = tid >> 5, lane = tid & 31;
    u32 dbase = (smem_u32(dynraw) + 1023u) & ~1023u;

    const __nv_bfloat16* Agh = ((MODE == 1) ? g_Th : g_Sh) + (size_t)bi * TDIM * DIM;
    const __nv_bfloat16* Agl = ((MODE == 1) ? g_Tl : g_Sl) + (size_t)bi * TDIM * DIM;
    const __nv_bfloat16* Bgh = ((MODE == 0) ? g_Sh : g_Th) + (size_t)bj * TDIM * DIM;
    const __nv_bfloat16* Bgl = ((MODE == 0) ? g_Sl : g_Tl) + (size_t)bj * TDIM * DIM;

    if (tid < TDIM) {
        naS[tid] = ((MODE == 1) ? g_tt : g_ss)[bi * TDIM + tid];
        if (MODE == 2) sRow[tid] = ~0ull;
    } else {
        nbS[tid - TDIM] = ((MODE == 0) ? g_ss : g_tt)[bj * TDIM + tid - TDIM];
        if (MODE == 2) sCol[tid - TDIM] = ~0ull;
    }

    const __nv_bfloat16* srcs[4] = {Agh, Agl, Bgh, Bgl};

    // ---- issue chunk 0 loads ----
    {
        u32 sb = dbase;
        #pragma unroll
        for (int t = 0; t < 4; t++)
            #pragma unroll
            for (int rep = 0; rep < 4; rep++) {
                int idx = rep * 256 + tid;
                int row = idx >> 3, seg = idx & 7;
                cp16(sb + t * OPB + swz(row, seg * 16),
                     srcs[t] + (size_t)row * DIM + seg * 8);
            }
        CP_COMMIT();
    }

    float acc[2][8][4];
    #pragma unroll
    for (int mf = 0; mf < 2; mf++)
        #pragma unroll
        for (int nf = 0; nf < 8; nf++)
            #pragma unroll
            for (int e = 0; e < 4; e++) acc[mf][nf][e] = 0.f;

    int mrow0 = (wid & 3) * 32;
    int ncol0 = (wid >> 2) * 64;
    // ldmatrix lane addressing
    int a_row = lane & 15;
    int a_k   = (lane >> 4) * 8;
    int b_row = (lane & 7) + ((lane >> 4) ? 8 : 0);
    int b_k   = ((lane >> 3) & 1) * 8;

    #pragma unroll
    for (int c = 0; c < NCH; c++) {
        if (c + 1 < NCH) {
            u32 sb = dbase + ((c + 1) & 1) * STAGEB;
            #pragma unroll
            for (int t = 0; t < 4; t++)
                #pragma unroll
                for (int rep = 0; rep < 4; rep++) {
                    int idx = rep * 256 + tid;
                    int row = idx >> 3, seg = idx & 7;
                    cp16(sb + t * OPB + swz(row, seg * 16),
                         srcs[t] + (size_t)row * DIM + (c + 1) * KC + seg * 8);
                }
            CP_COMMIT();
            CP_WAIT(1);
        } else {
            CP_WAIT(0);
        }
        __syncthreads();

        u32 sb = dbase + (c & 1) * STAGEB;
        #pragma unroll
        for (int ks = 0; ks < KC / 16; ks++) {
            u32 a[2][2][4];
            #pragma unroll
            for (int hl = 0; hl < 2; hl++)
                #pragma unroll
                for (int mf = 0; mf < 2; mf++)
                    ldsm4(a[hl][mf],
                          sb + hl * OPB + swz(mrow0 + mf * 16 + a_row, (ks * 16 + a_k) * 2));
            u32 b[2][8][2];
            #pragma unroll
            for (int hl = 0; hl < 2; hl++)
                #pragma unroll
                for (int np = 0; np < 4; np++) {
                    u32 r[4];
                    ldsm4(r, sb + (2 + hl) * OPB +
                             swz(ncol0 + np * 16 + b_row, (ks * 16 + b_k) * 2));
                    b[hl][2 * np][0] = r[0]; b[hl][2 * np][1] = r[1];
                    b[hl][2 * np + 1][0] = r[2]; b[hl][2 * np + 1][1] = r[3];
                }
            #pragma unroll
            for (int mf = 0; mf < 2; mf++)
                #pragma unroll
                for (int nf = 0; nf < 8; nf++) {
                    hmma(acc[mf][nf], a[0][mf], b[0][nf]);  // ah*bh
                    hmma(acc[mf][nf], a[0][mf], b[1][nf]);  // ah*bl
                    hmma(acc[mf][nf], a[1][mf], b[0][nf]);  // al*bh
                }
        }
        __syncthreads();
    }

    // ---- register-direct epilogue ----
    float nib = g_neg_inv_bw16;
    float myna[4], mynb[16];
    #pragma unroll
    for (int q = 0; q < 4; q++)
        myna[q] = naS[mrow0 + (q >> 1) * 16 + (q & 1) * 8 + (lane >> 2)];
    #pragma unroll
    for (int nf = 0; nf < 8; nf++)
        #pragma unroll
        for (int bb = 0; bb < 2; bb++)
            mynb[nf * 2 + bb] = nbS[ncol0 + nf * 8 + (lane & 3) * 2 + bb];

    float part = 0.f;
    ull rk[4], ck[16];
    if (MODE == 2) {
        #pragma unroll
        for (int q = 0; q < 4; q++) rk[q] = ~0ull;
        #pragma unroll
        for (int q = 0; q < 16; q++) ck[q] = ~0ull;
    }

    #pragma unroll
    for (int mf = 0; mf < 2; mf++)
        #pragma unroll
        for (int nf = 0; nf < 8; nf++)
            #pragma unroll
            for (int e = 0; e < 4; e++) {
                int eh = e >> 1, el = e & 1;
                float d2 = myna[mf * 2 + eh] + mynb[nf * 2 + el] - 2.f * acc[mf][nf][e];
                float ex = __expf(d2 * nib);
                float e2 = ex * ex, e4 = e2 * e2, e8 = e4 * e4;
                part += ex + e2 + e4 + e8 + e8 * e8;
                if (MODE == 2) {
                    float d2c = fmaxf(d2, 0.f);
                    ull key = ((ull)__float_as_uint(d2c)) << 32;
                    int rloc = mrow0 + mf * 16 + eh * 8 + (lane >> 2);
                    int cloc = ncol0 + nf * 8 + (lane & 3) * 2 + el;
                    ull kr = key | (unsigned)(bj * TDIM + cloc);
                    if (kr < rk[mf * 2 + eh]) rk[mf * 2 + eh] = kr;
                    ull kc = key | (unsigned)(bi * TDIM + rloc);
                    if (kc < ck[nf * 2 + el]) ck[nf * 2 + el] = kc;
                }
            }

    if (MODE == 2) {
        // row keys: reduce across the 4 lanes sharing each row (xor 1, 2)
        #pragma unroll
        for (int q = 0; q < 4; q++) {
            ull v = rk[q];
            #pragma unroll
            for (int o = 1; o <= 2; o <<= 1) {
                ull w = __shfl_xor_sync(0xffffffffu, v, o);
                if (w < v) v = w;
            }
            rk[q] = v;
        }
        if ((lane & 3) == 0) {
            #pragma unroll
            for (int q = 0; q < 4; q++)
                atomicMin(&sRow[mrow0 + (q >> 1) * 16 + (q & 1) * 8 + (lane >> 2)], rk[q]);
        }
        // col keys: reduce across the 8 lanes sharing each column (xor 4, 8, 16)
        #pragma unroll
        for (int q = 0; q < 16; q++) {
            ull v = ck[q];
            #pragma unroll
            for (int o = 4; o <= 16; o <<= 1) {
                ull w = __shfl_xor_sync(0xffffffffu, v, o);
                if (w < v) v = w;
            }
            ck[q] = v;
        }
        if (lane < 4) {
            #pragma unroll
            for (int q = 0; q < 16; q++)
                atomicMin(&sCol[ncol0 + (q >> 1) * 8 + lane * 2 + (q & 1)], ck[q]);
        }
    }

    if (MODE != 2 && bi != bj) part *= 2.f;
    for (int o = 16; o; o >>= 1) part += __shfl_down_sync(0xffffffffu, part, o);
    if (lane == 0) atomicAdd(&g_ksum[MODE], (double)part);

    if (MODE == 2) {
        __syncthreads();
        if (tid < TDIM) atomicMin(&g_min_row[bi * TDIM + tid], sRow[tid]);
        else            atomicMin(&g_min_col[bj * TDIM + tid - TDIM], sCol[tid - TDIM]);
    }
}

// ---------------- distillation ----------------
__device__ __forceinline__ float distill_row(const float* te, const float* st) {
    float mt = te[0], ms = st[0];
    #pragma unroll
    for (int c = 1; c < NCLS; c++) { mt = fmaxf(mt, te[c]); ms = fmaxf(ms, st[c]); }
    float set = 0.f, ses = 0.f;
    #pragma unroll
    for (int c = 0; c < NCLS; c++) { set += __expf(te[c] - mt); ses += __expf(st[c] - ms); }
    float lses = ms + __logf(ses);
    float inv = 1.f / set;
    float acc = 0.f;
    #pragma unroll
    for (int c = 0; c < NCLS; c++)
        acc += __expf(te[c] - mt) * inv * (lses - st[c]);
    return acc;
}

__global__ void dis_kernel(const float* __restrict__ sclf, const float* __restrict__ tclf) {
    int i = blockIdx.x * blockDim.x + threadIdx.x;
    float loss = 0.f;
    if (i < NSAMP) {
        int mi  = (int)(g_min_row[i] & 0xffffffffull);
        int mti = (int)(g_min_col[i] & 0xffffffffull);
        loss = distill_row(sclf + i * NCLS, tclf + mi * NCLS)
             + distill_row(sclf + mti * NCLS, tclf + i * NCLS);
    }
    for (int o = 16; o; o >>= 1) loss += __shfl_down_sync(0xffffffffu, loss, o);
    if ((threadIdx.x & 31) == 0) atomicAdd(&g_dis_sum, (double)loss);
}

__global__ void finalize_kernel(float* __restrict__ out) {
    out[0] = (float)(g_clf_sum / (double)NSAMP);
    out[1] = (float)(g_dis_sum / (double)NSAMP);
    out[2] = (float)((g_ksum[0] + g_ksum[1] - 2.0 * g_ksum[2]) /
                     ((double)NSAMP * (double)NSAMP));
}

// ---------------- launch ----------------
extern "C" void kernel_launch(void* const* d_in, const int* in_sizes, int n_in,
                              void* d_out, int out_size) {
    const float* S    = (const float*)d_in[0];
    const float* T    = (const float*)d_in[1];
    const float* sclf = (const float*)d_in[2];
    const float* tclf = (const float*)d_in[3];
    const int*   lab  = (const int*)d_in[4];
    float* out = (float*)d_out;

    cudaFuncSetAttribute(pair_mma<0>, cudaFuncAttributeMaxDynamicSharedMemorySize, SMEM_DYN);
    cudaFuncSetAttribute(pair_mma<1>, cudaFuncAttributeMaxDynamicSharedMemorySize, SMEM_DYN);
    cudaFuncSetAttribute(pair_mma<2>, cudaFuncAttributeMaxDynamicSharedMemorySize, SMEM_DYN);

    init_kernel<<<16, 256>>>();
    detect_labels<<<1, 256>>>(lab);
    preprocess<<<(2 * NSAMP) / 32, 256>>>(S, T);
    bandwidth_kernel<<<1, 256>>>();
    clf_kernel<<<16, 256>>>(sclf, lab);

    dim3 grid(NSAMP / TDIM, NSAMP / TDIM);
    pair_mma<0><<<grid, 256, SMEM_DYN>>>();
    pair_mma<1><<<grid, 256, SMEM_DYN>>>();
    pair_mma<2><<<grid, 256, SMEM_DYN>>>();

    dis_kernel<<<16, 256>>>(sclf, tclf);
    finalize_kernel<<<1, 1>>>(out);
}

// round 11
// speedup vs baseline: 2.9834x; 1.1636x over previous
#include <cuda_runtime.h>
#include <cuda_bf16.h>

typedef unsigned long long ull;
typedef unsigned int u32;

#define NSAMP 4096
#define DIM   256
#define NCLS  6
#define TDIM  128
#define KC    32
#define NCH   (DIM / KC)            // 8
#define OPB   (TDIM * KC * 2)       // 8192 bytes per operand tile
#define STAGEB (4 * OPB)            // 32768 per stage (Ah,Al,Bh,Bl)
#define SMEM_DYN (2 * STAGEB + 1024)

#define NT0 528                      // 32*33/2 triangular tiles
#define GRID_ALL (2 * NT0 + 1024)    // 2080

// ---------------- device scratch ----------------
__device__ __align__(1024) __nv_bfloat16 g_Sh[NSAMP * DIM];
__device__ __align__(1024) __nv_bfloat16 g_Sl[NSAMP * DIM];
__device__ __align__(1024) __nv_bfloat16 g_Th[NSAMP * DIM];
__device__ __align__(1024) __nv_bfloat16 g_Tl[NSAMP * DIM];
__device__ float  g_ss[NSAMP];
__device__ float  g_tt[NSAMP];
__device__ float  g_colsum[DIM];
__device__ double g_sqsum;
__device__ float  g_neg_inv_bw16;
__device__ ull    g_min_row[NSAMP];
__device__ ull    g_min_col[NSAMP];
__device__ double g_ksum[3];
__device__ double g_clf_sum;
__device__ double g_dis_sum;
__device__ int    g_label64;
__device__ u32    g_done_ctr;

// ---------------- PTX helpers (baseline ISA only) ----------------
__device__ __forceinline__ u32 smem_u32(const void* p) {
    u32 a;
    asm("{ .reg .u64 t; cvta.to.shared.u64 t, %1; cvt.u32.u64 %0, t; }" : "=r"(a) : "l"(p));
    return a;
}
__device__ __forceinline__ void cp16(u32 dst, const void* src) {
    asm volatile("cp.async.cg.shared.global [%0], [%1], 16;" :: "r"(dst), "l"(src));
}
#define CP_COMMIT() asm volatile("cp.async.commit_group;")
#define CP_WAIT(n)  asm volatile("cp.async.wait_group %0;" :: "n"(n))

__device__ __forceinline__ void ldsm4(u32* r, u32 addr) {
    asm volatile("ldmatrix.sync.aligned.m8n8.x4.shared.b16 {%0,%1,%2,%3}, [%4];"
        : "=r"(r[0]), "=r"(r[1]), "=r"(r[2]), "=r"(r[3]) : "r"(addr));
}
__device__ __forceinline__ void hmma(float* d, const u32* a, const u32* b) {
    asm volatile(
        "mma.sync.aligned.m16n8k16.row.col.f32.bf16.bf16.f32 "
        "{%0,%1,%2,%3}, {%4,%5,%6,%7}, {%8,%9}, {%0,%1,%2,%3};"
        : "+f"(d[0]), "+f"(d[1]), "+f"(d[2]), "+f"(d[3])
        : "r"(a[0]), "r"(a[1]), "r"(a[2]), "r"(a[3]), "r"(b[0]), "r"(b[1]));
}

// 64B-row XOR swizzle (SW64): conflict-free for 8-row x 16B ldmatrix reads
__device__ __forceinline__ u32 swz64(u32 row, u32 colbytes) {
    u32 off = row * 64u + colbytes;
    return off ^ ((off >> 3) & 0x30u);
}

// ---------------- init (+label detect) ----------------
__global__ void init_kernel(const int* __restrict__ w) {
    int i = blockIdx.x * blockDim.x + threadIdx.x;
    if (i < NSAMP) { g_min_row[i] = ~0ull; g_min_col[i] = ~0ull; }
    if (i < DIM)   g_colsum[i] = 0.f;
    if (i < 3)     g_ksum[i] = 0.0;
    if (i == 0) { g_sqsum = 0.0; g_clf_sum = 0.0; g_dis_sum = 0.0; g_done_ctr = 0u; }

    if (blockIdx.x == 0) {
        __shared__ int any;
        if (threadIdx.x == 0) any = 0;
        __syncthreads();
        for (int k = 1 + 2 * threadIdx.x; k < NSAMP; k += 2 * blockDim.x)
            if (w[k] != 0) any = 1;
        __syncthreads();
        if (threadIdx.x == 0) g_label64 = (any == 0) ? 1 : 0;
    }
}

// fused: bf16 hi/lo split + row norms + column sums + total squared sum
__global__ void preprocess(const float* __restrict__ S, const float* __restrict__ T) {
    __shared__ float tile[32][DIM + 1];
    int r0 = blockIdx.x * 32;
    bool isS = (r0 < NSAMP);
    int rloc = isS ? r0 : (r0 - NSAMP);
    const float* X = isS ? (S + (size_t)r0 * DIM) : (T + (size_t)rloc * DIM);
    __nv_bfloat16* H = isS ? (g_Sh + (size_t)r0 * DIM) : (g_Th + (size_t)rloc * DIM);
    __nv_bfloat16* L = isS ? (g_Sl + (size_t)r0 * DIM) : (g_Tl + (size_t)rloc * DIM);

    int tid = threadIdx.x;
    for (int i = tid; i < 32 * DIM; i += 256) {
        float v = X[i];
        tile[i >> 8][i & 255] = v;
        __nv_bfloat16 h = __float2bfloat16(v);
        H[i] = h;
        L[i] = __float2bfloat16(v - __bfloat162float(h));
    }
    __syncthreads();

    int wid = tid >> 5, lane = tid & 31;
    float dsum = 0.f;
    #pragma unroll
    for (int q = 0; q < 4; q++) {
        int rr = wid * 4 + q;
        float s = 0.f;
        for (int c = lane; c < DIM; c += 32) { float v = tile[rr][c]; s += v * v; }
        for (int o = 16; o; o >>= 1) s += __shfl_down_sync(0xffffffffu, s, o);
        if (lane == 0) {
            if (isS) g_ss[r0 + rr] = s; else g_tt[rloc + rr] = s;
            dsum += s;
        }
    }
    if (lane == 0) atomicAdd(&g_sqsum, (double)dsum);

    float cs = 0.f;
    #pragma unroll
    for (int rr = 0; rr < 32; rr++) cs += tile[rr][tid];
    atomicAdd(&g_colsum[tid], cs);
}

// blocks 0..15: cross-entropy rows; block 16: bandwidth closed form
__global__ void bw_clf_kernel(const float* __restrict__ sclf, const int* __restrict__ lw) {
    if (blockIdx.x == 16) {
        float cs = g_colsum[threadIdx.x];
        double p = (double)cs * (double)cs;
        for (int o = 16; o; o >>= 1) p += __shfl_down_sync(0xffffffffu, p, o);
        __shared__ double ws[8];
        if ((threadIdx.x & 31) == 0) ws[threadIdx.x >> 5] = p;
        __syncthreads();
        if (threadIdx.x == 0) {
            double ssv = 0.0;
            #pragma unroll
            for (int k = 0; k < 8; k++) ssv += ws[k];
            double n = 2.0 * NSAMP;
            double sumL2 = 2.0 * n * g_sqsum - 2.0 * ssv;
            double b = sumL2 / (n * n - n) / 4.0;
            g_neg_inv_bw16 = (float)(-1.0 / (b * 16.0));
        }
        return;
    }
    int i = blockIdx.x * blockDim.x + threadIdx.x;
    const float* x = sclf + i * NCLS;
    float m = x[0];
    #pragma unroll
    for (int c = 1; c < NCLS; c++) m = fmaxf(m, x[c]);
    float se = 0.f;
    #pragma unroll
    for (int c = 0; c < NCLS; c++) se += __expf(x[c] - m);
    float lse = m + __logf(se);
    int lab = g_label64 ? lw[2 * i] : lw[i];
    float loss = lse - x[lab];
    for (int o = 16; o; o >>= 1) loss += __shfl_down_sync(0xffffffffu, loss, o);
    if ((threadIdx.x & 31) == 0) atomicAdd(&g_clf_sum, (double)loss);
}

// ---------------- merged mma.sync pair kernel ----------------
// blockIdx.x decodes: [0,528) SxS upper-tri, [528,1056) TxT upper-tri,
// [1056,2080) SxT full (+argmin)
__global__ __launch_bounds__(256, 2) void pair_all() {
    int idx = blockIdx.x;
    int mode, bi, bj;
    if (idx < 2 * NT0) {
        mode = (idx < NT0) ? 0 : 1;
        int q = (idx < NT0) ? idx : idx - NT0;
        int b = 0;
        while (q >= 32 - b) { q -= 32 - b; b++; }
        bi = b; bj = b + q;
    } else {
        mode = 2; int q = idx - 2 * NT0;
        bi = q >> 5; bj = q & 31;
    }

    extern __shared__ char dynraw[];
    __shared__ float naS[TDIM], nbS[TDIM];
    __shared__ ull   sRow[TDIM], sCol[TDIM];

    int tid = threadIdx.x, wid = tid >> 5, lane = tid & 31;
    u32 dbase = (smem_u32(dynraw) + 1023u) & ~1023u;

    const __nv_bfloat16* Agh = ((mode == 1) ? g_Th : g_Sh) + (size_t)bi * TDIM * DIM;
    const __nv_bfloat16* Agl = ((mode == 1) ? g_Tl : g_Sl) + (size_t)bi * TDIM * DIM;
    const __nv_bfloat16* Bgh = ((mode == 0) ? g_Sh : g_Th) + (size_t)bj * TDIM * DIM;
    const __nv_bfloat16* Bgl = ((mode == 0) ? g_Sl : g_Tl) + (size_t)bj * TDIM * DIM;

    if (tid < TDIM) {
        naS[tid] = ((mode == 1) ? g_tt : g_ss)[bi * TDIM + tid];
        sRow[tid] = ~0ull;
    } else {
        nbS[tid - TDIM] = ((mode == 0) ? g_ss : g_tt)[bj * TDIM + tid - TDIM];
        sCol[tid - TDIM] = ~0ull;
    }

    const __nv_bfloat16* srcs[4] = {Agh, Agl, Bgh, Bgl};

    // issue chunk 0
    {
        u32 sb = dbase;
        #pragma unroll
        for (int t = 0; t < 4; t++)
            #pragma unroll
            for (int rep = 0; rep < 2; rep++) {
                int ix = rep * 256 + tid;           // 0..511
                int row = ix >> 2, seg = ix & 3;
                cp16(sb + t * OPB + swz64(row, seg * 16),
                     srcs[t] + (size_t)row * DIM + seg * 8);
            }
        CP_COMMIT();
    }

    float acc[2][8][4];
    #pragma unroll
    for (int mf = 0; mf < 2; mf++)
        #pragma unroll
        for (int nf = 0; nf < 8; nf++)
            #pragma unroll
            for (int e = 0; e < 4; e++) acc[mf][nf][e] = 0.f;

    int mrow0 = (wid & 3) * 32;
    int ncol0 = (wid >> 2) * 64;
    int a_row = lane & 15;
    int a_kb  = (lane >> 4) * 16;           // bytes
    int b_row = (lane & 7) + ((lane >> 4) ? 8 : 0);
    int b_kb  = ((lane >> 3) & 1) * 16;     // bytes

    for (int c = 0; c < NCH; c++) {
        if (c + 1 < NCH) {
            u32 sb = dbase + ((c + 1) & 1) * STAGEB;
            #pragma unroll
            for (int t = 0; t < 4; t++)
                #pragma unroll
                for (int rep = 0; rep < 2; rep++) {
                    int ix = rep * 256 + tid;
                    int row = ix >> 2, seg = ix & 3;
                    cp16(sb + t * OPB + swz64(row, seg * 16),
                         srcs[t] + (size_t)row * DIM + (c + 1) * KC + seg * 8);
                }
            CP_COMMIT();
            CP_WAIT(1);
        } else {
            CP_WAIT(0);
        }
        __syncthreads();

        u32 sb = dbase + (c & 1) * STAGEB;
        #pragma unroll
        for (int ks = 0; ks < KC / 16; ks++) {
            u32 ah[2][4], al[2][4];
            #pragma unroll
            for (int mf = 0; mf < 2; mf++) {
                ldsm4(ah[mf], sb + 0 * OPB + swz64(mrow0 + mf * 16 + a_row, ks * 32 + a_kb));
                ldsm4(al[mf], sb + 1 * OPB + swz64(mrow0 + mf * 16 + a_row, ks * 32 + a_kb));
            }
            u32 bb[8][2];
            // ---- phase 1: B-hi -> hh + lh ----
            #pragma unroll
            for (int np = 0; np < 4; np++) {
                u32 r[4];
                ldsm4(r, sb + 2 * OPB + swz64(ncol0 + np * 16 + b_row, ks * 32 + b_kb));
                bb[2 * np][0] = r[0]; bb[2 * np][1] = r[1];
                bb[2 * np + 1][0] = r[2]; bb[2 * np + 1][1] = r[3];
            }
            #pragma unroll
            for (int nf = 0; nf < 8; nf++) {
                hmma(acc[0][nf], ah[0], bb[nf]);
                hmma(acc[1][nf], ah[1], bb[nf]);
                hmma(acc[0][nf], al[0], bb[nf]);
                hmma(acc[1][nf], al[1], bb[nf]);
            }
            // ---- phase 2: B-lo -> hl ----
            #pragma unroll
            for (int np = 0; np < 4; np++) {
                u32 r[4];
                ldsm4(r, sb + 3 * OPB + swz64(ncol0 + np * 16 + b_row, ks * 32 + b_kb));
                bb[2 * np][0] = r[0]; bb[2 * np][1] = r[1];
                bb[2 * np + 1][0] = r[2]; bb[2 * np + 1][1] = r[3];
            }
            #pragma unroll
            for (int nf = 0; nf < 8; nf++) {
                hmma(acc[0][nf], ah[0], bb[nf]);
                hmma(acc[1][nf], ah[1], bb[nf]);
            }
        }
        __syncthreads();
    }

    // ---- register-direct epilogue ----
    float nib = g_neg_inv_bw16;
    float myna[4];
    #pragma unroll
    for (int q = 0; q < 4; q++)
        myna[q] = naS[mrow0 + (q >> 1) * 16 + (q & 1) * 8 + (lane >> 2)];

    float part = 0.f;
    ull rk[4];
    #pragma unroll
    for (int q = 0; q < 4; q++) rk[q] = ~0ull;

    #pragma unroll
    for (int nf = 0; nf < 8; nf++) {
        float nb0 = nbS[ncol0 + nf * 8 + (lane & 3) * 2 + 0];
        float nb1 = nbS[ncol0 + nf * 8 + (lane & 3) * 2 + 1];
        ull ck0 = ~0ull, ck1 = ~0ull;
        #pragma unroll
        for (int mf = 0; mf < 2; mf++)
            #pragma unroll
            for (int e = 0; e < 4; e++) {
                int eh = e >> 1, el = e & 1;
                float d2 = myna[mf * 2 + eh] + (el ? nb1 : nb0) - 2.f * acc[mf][nf][e];
                float ex = __expf(d2 * nib);
                float e2 = ex * ex, e4 = e2 * e2, e8 = e4 * e4;
                part += ex + e2 + e4 + e8 + e8 * e8;
                if (mode == 2) {
                    float d2c = fmaxf(d2, 0.f);
                    ull key = ((ull)__float_as_uint(d2c)) << 32;
                    int rloc = mrow0 + mf * 16 + eh * 8 + (lane >> 2);
                    int cloc = ncol0 + nf * 8 + (lane & 3) * 2 + el;
                    ull kr = key | (unsigned)(bj * TDIM + cloc);
                    if (kr < rk[mf * 2 + eh]) rk[mf * 2 + eh] = kr;
                    ull kc = key | (unsigned)(bi * TDIM + rloc);
                    if (el) { if (kc < ck1) ck1 = kc; } else { if (kc < ck0) ck0 = kc; }
                }
            }
        if (mode == 2) {
            #pragma unroll
            for (int o = 4; o <= 16; o <<= 1) {
                ull w0 = __shfl_xor_sync(0xffffffffu, ck0, o);
                ull w1 = __shfl_xor_sync(0xffffffffu, ck1, o);
                if (w0 < ck0) ck0 = w0;
                if (w1 < ck1) ck1 = w1;
            }
            if (lane < 4) {
                atomicMin(&sCol[ncol0 + nf * 8 + lane * 2 + 0], ck0);
                atomicMin(&sCol[ncol0 + nf * 8 + lane * 2 + 1], ck1);
            }
        }
    }

    if (mode == 2) {
        #pragma unroll
        for (int q = 0; q < 4; q++) {
            ull v = rk[q];
            #pragma unroll
            for (int o = 1; o <= 2; o <<= 1) {
                ull w = __shfl_xor_sync(0xffffffffu, v, o);
                if (w < v) v = w;
            }
            rk[q] = v;
        }
        if ((lane & 3) == 0) {
            #pragma unroll
            for (int q = 0; q < 4; q++)
                atomicMin(&sRow[mrow0 + (q >> 1) * 16 + (q & 1) * 8 + (lane >> 2)], rk[q]);
        }
    }

    if (mode != 2 && bi != bj) part *= 2.f;
    for (int o = 16; o; o >>= 1) part += __shfl_down_sync(0xffffffffu, part, o);
    if (lane == 0) atomicAdd(&g_ksum[mode], (double)part);

    if (mode == 2) {
        __syncthreads();
        if (tid < TDIM) atomicMin(&g_min_row[bi * TDIM + tid], sRow[tid]);
        else            atomicMin(&g_min_col[bj * TDIM + tid - TDIM], sCol[tid - TDIM]);
    }
}

// ---------------- distillation + finalize (last block writes output) ----------------
__device__ __forceinline__ float distill_row(const float* te, const float* st) {
    float mt = te[0], ms = st[0];
    #pragma unroll
    for (int c = 1; c < NCLS; c++) { mt = fmaxf(mt, te[c]); ms = fmaxf(ms, st[c]); }
    float set = 0.f, ses = 0.f;
    #pragma unroll
    for (int c = 0; c < NCLS; c++) { set += __expf(te[c] - mt); ses += __expf(st[c] - ms); }
    float lses = ms + __logf(ses);
    float inv = 1.f / set;
    float acc = 0.f;
    #pragma unroll
    for (int c = 0; c < NCLS; c++)
        acc += __expf(te[c] - mt) * inv * (lses - st[c]);
    return acc;
}

__global__ void dis_final_kernel(const float* __restrict__ sclf,
                                 const float* __restrict__ tclf,
                                 float* __restrict__ out) {
    int i = blockIdx.x * blockDim.x + threadIdx.x;
    int mi  = (int)(g_min_row[i] & 0xffffffffull);
    int mti = (int)(g_min_col[i] & 0xffffffffull);
    float loss = distill_row(sclf + i * NCLS, tclf + mi * NCLS)
               + distill_row(sclf + mti * NCLS, tclf + i * NCLS);
    for (int o = 16; o; o >>= 1) loss += __shfl_down_sync(0xffffffffu, loss, o);
    if ((threadIdx.x & 31) == 0) atomicAdd(&g_dis_sum, (double)loss);

    __syncthreads();
    __threadfence();
    __shared__ u32 rank;
    if (threadIdx.x == 0) rank = atomicAdd(&g_done_ctr, 1u);
    __syncthreads();
    if (rank == gridDim.x - 1 && threadIdx.x == 0) {
        out[0] = (float)(g_clf_sum / (double)NSAMP);
        out[1] = (float)(g_dis_sum / (double)NSAMP);
        out[2] = (float)((g_ksum[0] + g_ksum[1] - 2.0 * g_ksum[2]) /
                         ((double)NSAMP * (double)NSAMP));
    }
}

// ---------------- launch ----------------
extern "C" void kernel_launch(void* const* d_in, const int* in_sizes, int n_in,
                              void* d_out, int out_size) {
    const float* S    = (const float*)d_in[0];
    const float* T    = (const float*)d_in[1];
    const float* sclf = (const float*)d_in[2];
    const float* tclf = (const float*)d_in[3];
    const int*   lab  = (const int*)d_in[4];
    float* out = (float*)d_out;

    cudaFuncSetAttribute(pair_all, cudaFuncAttributeMaxDynamicSharedMemorySize, SMEM_DYN);

    init_kernel<<<16, 256>>>(lab);
    preprocess<<<(2 * NSAMP) / 32, 256>>>(S, T);
    bw_clf_kernel<<<17, 256>>>(sclf, lab);
    pair_all<<<GRID_ALL, 256, SMEM_DYN>>>();
    dis_final_kernel<<<16, 256>>>(sclf, tclf, out);
}